// round 7
// baseline (speedup 1.0000x reference)
#include <cuda_runtime.h>

#define T_LEN 4096
#define D_DIM 1024
#define NCTA  128
#define CPC   8      // columns per CTA (= warps per CTA)

typedef unsigned long long ull;

// ---------------- scratch (device globals: no allocation allowed) -----------
__device__ float  g_Gr[T_LEN * D_DIM];
__device__ float  g_Gz[T_LEN * D_DIM];
__device__ float  g_Gn[T_LEN * D_DIM];
__device__ float  g_ys[T_LEN * D_DIM];          // plain h history (post GEMM)
__device__ float2 g_hs[T_LEN * D_DIM];          // {h, step_tag} fused word

// ---------------- PTX helpers ----------------------------------------------
__device__ __forceinline__ ull pack2(float lo, float hi) {
    ull r;
    asm("mov.b64 %0, {%1, %2};" : "=l"(r) : "f"(lo), "f"(hi));
    return r;
}
__device__ __forceinline__ void unpack2(ull v, float& lo, float& hi) {
    asm("mov.b64 {%0, %1}, %2;" : "=f"(lo), "=f"(hi) : "l"(v));
}
__device__ __forceinline__ void fma2(ull& d, ull a, ull b) {
    asm("fma.rn.f32x2 %0, %1, %2, %0;" : "+l"(d) : "l"(a), "l"(b));
}
__device__ __forceinline__ float4 ldvol_f4(const float4* p) {
    float4 v;
    asm volatile("ld.volatile.global.v4.f32 {%0,%1,%2,%3}, [%4];"
                 : "=f"(v.x), "=f"(v.y), "=f"(v.z), "=f"(v.w) : "l"(p));
    return v;
}
__device__ __forceinline__ void stvol_f2(float2* p, float a, float b) {
    asm volatile("st.volatile.global.v2.f32 [%0], {%1,%2};" :: "l"(p), "f"(a), "f"(b));
}

// ---------------- tag clear (fresh each graph replay) -----------------------
__global__ void clear_tags_kernel() {
    size_t i = (size_t)blockIdx.x * blockDim.x + threadIdx.x;   // float4 index
    ((float4*)g_hs)[i] = make_float4(0.f, 0.f, 0.f, 0.f);
}

// ---------------- fp32 GEMM: C = (relu?)(A) @ B + bias, 128x128 / 8x8 ------
template <bool RELU_A>
__global__ void __launch_bounds__(256) gemm128_kernel(
    const float* __restrict__ A, const float* __restrict__ B,
    const float* __restrict__ bias, float* __restrict__ C,
    int M, int N, int K)
{
    __shared__ float As[8][128];   // As[k][m] (transposed)
    __shared__ float Bs[8][128];   // Bs[k][n]

    const int tid = threadIdx.x;
    const int bm = blockIdx.y << 7, bn = blockIdx.x << 7;

    const int arow = tid >> 1;             // 0..127
    const int acol = (tid & 1) << 2;       // 0 or 4
    const int brow = tid >> 5;             // 0..7
    const int bcol = (tid & 31) << 2;      // 0..124

    const float* Ap = A + (size_t)(bm + arow) * K + acol;
    const float* Bp = B + (size_t)brow * N + bn + bcol;

    const int tx = tid & 15, ty = tid >> 4;

    float acc[8][8];
#pragma unroll
    for (int i = 0; i < 8; i++)
#pragma unroll
        for (int j = 0; j < 8; j++) acc[i][j] = 0.f;

    float4 a4 = *(const float4*)Ap;
    float4 b4 = *(const float4*)Bp;

    for (int kb = 0; kb < K; kb += 8) {
        float4 av = a4, bv = b4;
        if (RELU_A) {
            av.x = fmaxf(av.x, 0.f); av.y = fmaxf(av.y, 0.f);
            av.z = fmaxf(av.z, 0.f); av.w = fmaxf(av.w, 0.f);
        }
        As[acol + 0][arow] = av.x;
        As[acol + 1][arow] = av.y;
        As[acol + 2][arow] = av.z;
        As[acol + 3][arow] = av.w;
        *(float4*)&Bs[brow][bcol] = bv;
        __syncthreads();

        if (kb + 8 < K) {                       // prefetch next k-slice
            a4 = *(const float4*)(Ap + kb + 8);
            b4 = *(const float4*)(Bp + (size_t)(kb + 8) * N);
        }

#pragma unroll
        for (int kk = 0; kk < 8; kk++) {
            float a8[8], b8[8];
            *(float4*)(a8)     = *(const float4*)&As[kk][ty << 3];
            *(float4*)(a8 + 4) = *(const float4*)&As[kk][(ty << 3) + 4];
            *(float4*)(b8)     = *(const float4*)&Bs[kk][tx << 3];
            *(float4*)(b8 + 4) = *(const float4*)&Bs[kk][(tx << 3) + 4];
#pragma unroll
            for (int i = 0; i < 8; i++)
#pragma unroll
                for (int j = 0; j < 8; j++)
                    acc[i][j] = fmaf(a8[i], b8[j], acc[i][j]);
        }
        __syncthreads();
    }

    float bb[8];
    *(float4*)(bb)     = *(const float4*)&bias[bn + (tx << 3)];
    *(float4*)(bb + 4) = *(const float4*)&bias[bn + (tx << 3) + 4];
#pragma unroll
    for (int i = 0; i < 8; i++) {
        float* Cp = C + (size_t)(bm + (ty << 3) + i) * N + bn + (tx << 3);
        *(float4*)(Cp)     = make_float4(acc[i][0] + bb[0], acc[i][1] + bb[1],
                                         acc[i][2] + bb[2], acc[i][3] + bb[3]);
        *(float4*)(Cp + 4) = make_float4(acc[i][4] + bb[4], acc[i][5] + bb[5],
                                         acc[i][6] + bb[6], acc[i][7] + bb[7]);
    }
}

// ---------------- persistent GRU recurrence ---------------------------------
// 128 CTAs x 256 threads (R2 transport: fused {h,tag} words, double-buffered
// smem h, single bar/step). NEW: 2-deep pipelined polling — a second volatile
// load of each slot is already in flight while the previous value is checked,
// halving the poll-period quantization of the detect latency.
__global__ void __launch_bounds__(256, 1) gru_recurrence_kernel(
    const float* __restrict__ Whr, const float* __restrict__ Whz,
    const float* __restrict__ Whn, const float* __restrict__ bhn,
    const float* __restrict__ init_state)
{
    __shared__ float sh_h[2][D_DIM];       // double buffer: h rows

    const int tid  = threadIdx.x;
    const int warp = tid >> 5, lane = tid & 31;
    const int col  = blockIdx.x * CPC + warp;

    // ---- one-time: weight slice into registers (48 packed f32x2 / gate) ----
    ull wr[16], wz[16], wn[16];
#pragma unroll
    for (int i = 0; i < 16; i++) {
        const int k0 = 2 * (lane + 32 * i);
        const size_t o0 = (size_t)k0 * D_DIM + col;
        const size_t o1 = (size_t)(k0 + 1) * D_DIM + col;
        wr[i] = pack2(Whr[o0], Whr[o1]);
        wz[i] = pack2(Whz[o0], Whz[o1]);
        wn[i] = pack2(Whn[o0], Whn[o1]);
    }
    const float bhn_c = bhn[col];

    float h_prev = init_state[col];
    float gr_c = g_Gr[col], gz_c = g_Gz[col], gn_c = g_Gn[col];

    const int s0 = tid, s1 = tid + 256;    // this thread's two float4 slots

    for (int t = 0; t < T_LEN; t++) {
        float* dst = sh_h[t & 1];

        // ---- prefetch next step's gate pre-activations (independent) ----
        float grn = 0.f, gzn = 0.f, gnn = 0.f;
        if (lane == 0 && t + 1 < T_LEN) {
            const size_t o = (size_t)(t + 1) * D_DIM + col;
            grn = __ldg(&g_Gr[o]); gzn = __ldg(&g_Gz[o]); gnn = __ldg(&g_Gn[o]);
        }

        // ---- stage h_{t-1} with 2-deep pipelined dual-slot polling ----
        if (t == 0) {
            float4 v = ((const float4*)init_state)[tid];
            *(float4*)&dst[tid << 2] = v;
        } else {
            const float4* src = (const float4*)(g_hs + (size_t)(t - 1) * D_DIM);
            const unsigned tag = __float_as_uint((float)t);
            float4 a0 = ldvol_f4(src + s0);
            float4 b0 = ldvol_f4(src + s1);
            float4 a1 = ldvol_f4(src + s0);
            float4 b1 = ldvol_f4(src + s1);
            bool da = false, db = false;
            while (true) {
                if (!da && __float_as_uint(a0.y) == tag &&
                           __float_as_uint(a0.w) == tag) {
                    ((float2*)dst)[s0] = make_float2(a0.x, a0.z);
                    da = true;
                }
                if (!db && __float_as_uint(b0.y) == tag &&
                           __float_as_uint(b0.w) == tag) {
                    ((float2*)dst)[s1] = make_float2(b0.x, b0.z);
                    db = true;
                }
                if (da && db) break;
                a0 = a1; b0 = b1;                 // consume pipelined values
                if (!da) a1 = ldvol_f4(src + s0); // keep one in flight
                if (!db) b1 = ldvol_f4(src + s1);
            }
        }
        __syncthreads();   // staging complete; double buffer handles WAR

        // ---- packed dot products (3 gates, 2 accumulators each) ----
        const ull* h2 = (const ull*)dst;
        ull ar0 = 0, ar1 = 0, az0 = 0, az1 = 0, an0 = 0, an1 = 0;
#pragma unroll
        for (int i = 0; i < 16; i += 2) {
            ull h0 = h2[lane + 32 * i];
            ull h1 = h2[lane + 32 * (i + 1)];
            fma2(ar0, h0, wr[i]);  fma2(ar1, h1, wr[i + 1]);
            fma2(az0, h0, wz[i]);  fma2(az1, h1, wz[i + 1]);
            fma2(an0, h0, wn[i]);  fma2(an1, h1, wn[i + 1]);
        }
        float lo, hi, ar, az, an;
        unpack2(ar0, lo, hi); ar = lo + hi; unpack2(ar1, lo, hi); ar += lo + hi;
        unpack2(az0, lo, hi); az = lo + hi; unpack2(az1, lo, hi); az += lo + hi;
        unpack2(an0, lo, hi); an = lo + hi; unpack2(an1, lo, hi); an += lo + hi;

#pragma unroll
        for (int o = 16; o > 0; o >>= 1) {
            ar += __shfl_xor_sync(0xFFFFFFFFu, ar, o);
            az += __shfl_xor_sync(0xFFFFFFFFu, az, o);
            an += __shfl_xor_sync(0xFFFFFFFFu, an, o);
        }

        // ---- gate math + publish (lane 0 of each warp) ----
        if (lane == 0) {
            float er = __expf(-(gr_c + ar));
            float r  = __fdividef(1.f, 1.f + er);
            float ez = __expf(-(gz_c + az));
            float z  = __fdividef(1.f, 1.f + ez);
            float nx = gn_c + r * (an + bhn_c);
            float en = __expf(-2.f * nx);
            float n  = __fdividef(1.f - en, 1.f + en);      // tanh(nx)
            float hnew = n + z * (h_prev - n);
            // publish FIRST (critical path), history second
            stvol_f2(g_hs + (size_t)t * D_DIM + col, hnew, (float)(t + 1));
            g_ys[(size_t)t * D_DIM + col] = hnew;
            h_prev = hnew;
            gr_c = grn; gz_c = gzn; gn_c = gnn;
        }
    }
}

// ---------------- residual + layernorm (in-place on d_out) -----------------
__global__ void __launch_bounds__(256) layernorm_kernel(
    const float* __restrict__ xs, const float* __restrict__ ln_scale,
    const float* __restrict__ ln_bias, float* __restrict__ inout)
{
    __shared__ float red0[8], red1[8];
    const int t = blockIdx.x, tid = threadIdx.x;
    const float* xrow = xs + (size_t)t * D_DIM;
    float* yrow = inout + (size_t)t * D_DIM;

    float v[4];
    float s = 0.f, s2 = 0.f;
#pragma unroll
    for (int i = 0; i < 4; i++) {
        int idx = tid + i * 256;
        float y = xrow[idx] + yrow[idx];
        v[i] = y; s += y; s2 += y * y;
    }
#pragma unroll
    for (int o = 16; o > 0; o >>= 1) {
        s  += __shfl_xor_sync(0xFFFFFFFFu, s,  o);
        s2 += __shfl_xor_sync(0xFFFFFFFFu, s2, o);
    }
    const int warp = tid >> 5, lane = tid & 31;
    if (lane == 0) { red0[warp] = s; red1[warp] = s2; }
    __syncthreads();
    if (warp == 0) {
        float a = (lane < 8) ? red0[lane] : 0.f;
        float b = (lane < 8) ? red1[lane] : 0.f;
#pragma unroll
        for (int o = 4; o > 0; o >>= 1) {
            a += __shfl_xor_sync(0xFFFFFFFFu, a, o);
            b += __shfl_xor_sync(0xFFFFFFFFu, b, o);
        }
        if (lane == 0) { red0[0] = a; red1[0] = b; }
    }
    __syncthreads();

    const float mu   = red0[0] * (1.f / D_DIM);
    const float var  = red1[0] * (1.f / D_DIM) - mu * mu;
    const float rstd = rsqrtf(var + 1e-6f);
#pragma unroll
    for (int i = 0; i < 4; i++) {
        int idx = tid + i * 256;
        yrow[idx] = (v[i] - mu) * rstd * ln_scale[idx] + ln_bias[idx];
    }
}

// ---------------- launcher --------------------------------------------------
extern "C" void kernel_launch(void* const* d_in, const int* in_sizes, int n_in,
                              void* d_out, int out_size)
{
    const float* xs        = (const float*)d_in[0];
    const float* init_st   = (const float*)d_in[1];
    const float* Wir       = (const float*)d_in[2];
    const float* Wiz       = (const float*)d_in[3];
    const float* Win       = (const float*)d_in[4];
    const float* bir       = (const float*)d_in[5];
    const float* biz       = (const float*)d_in[6];
    const float* bin_      = (const float*)d_in[7];
    const float* Whr       = (const float*)d_in[8];
    const float* Whz       = (const float*)d_in[9];
    const float* Whn       = (const float*)d_in[10];
    const float* bhn       = (const float*)d_in[11];
    const float* Wl        = (const float*)d_in[12];
    const float* bl        = (const float*)d_in[13];
    const float* ln_scale  = (const float*)d_in[14];
    const float* ln_bias   = (const float*)d_in[15];
    float* out = (float*)d_out;

    void *pGr, *pGz, *pGn, *pYs;
    cudaGetSymbolAddress(&pGr, g_Gr);
    cudaGetSymbolAddress(&pGz, g_Gz);
    cudaGetSymbolAddress(&pGn, g_Gn);
    cudaGetSymbolAddress(&pYs, g_ys);

    dim3 gemm_grid(D_DIM / 128, T_LEN / 128);   // (8, 32)

    // 1) clear h tags (graph-replay determinism)
    clear_tags_kernel<<<(T_LEN * D_DIM * 2 / 4) / 256, 256>>>();

    // 2) input-side gate pre-GEMMs (parallel over time)
    gemm128_kernel<false><<<gemm_grid, 256>>>(xs, Wir, bir, (float*)pGr,
                                              T_LEN, D_DIM, D_DIM);
    gemm128_kernel<false><<<gemm_grid, 256>>>(xs, Wiz, biz, (float*)pGz,
                                              T_LEN, D_DIM, D_DIM);
    gemm128_kernel<false><<<gemm_grid, 256>>>(xs, Win, bin_, (float*)pGn,
                                              T_LEN, D_DIM, D_DIM);

    // 3) sequential recurrence: persistent grid, register-resident weights
    gru_recurrence_kernel<<<NCTA, 256>>>(Whr, Whz, Whn, bhn, init_st);

    // 4) post dense: d_out = relu(ys) @ Wl + bl
    gemm128_kernel<true><<<gemm_grid, 256>>>((const float*)pYs, Wl, bl, out,
                                             T_LEN, D_DIM, D_DIM);

    // 5) residual + layernorm in-place on d_out
    layernorm_kernel<<<T_LEN, 256>>>(xs, ln_scale, ln_bias, out);
}

// round 8
// speedup vs baseline: 1.4182x; 1.4182x over previous
#include <cuda_runtime.h>

#define T_LEN 4096
#define D_DIM 1024
#define NCTA  128
#define CPC   8      // columns per CTA (= warps per CTA)
#define SENTINEL 0x7FC00001u   // NaN payload no real h can ever equal

typedef unsigned long long ull;

// ---------------- scratch (device globals: no allocation allowed) -----------
__device__ float g_Gr[T_LEN * D_DIM];
__device__ float g_Gz[T_LEN * D_DIM];
__device__ float g_Gn[T_LEN * D_DIM];
__device__ float g_h [T_LEN * D_DIM];   // h history; sentinel = not yet written

// ---------------- PTX helpers ----------------------------------------------
__device__ __forceinline__ ull pack2(float lo, float hi) {
    ull r;
    asm("mov.b64 %0, {%1, %2};" : "=l"(r) : "f"(lo), "f"(hi));
    return r;
}
__device__ __forceinline__ void unpack2(ull v, float& lo, float& hi) {
    asm("mov.b64 {%0, %1}, %2;" : "=f"(lo), "=f"(hi) : "l"(v));
}
__device__ __forceinline__ void fma2(ull& d, ull a, ull b) {
    asm("fma.rn.f32x2 %0, %1, %2, %0;" : "+l"(d) : "l"(a), "l"(b));
}
__device__ __forceinline__ float4 ldvol_f4(const float4* p) {
    float4 v;
    asm volatile("ld.volatile.global.v4.f32 {%0,%1,%2,%3}, [%4];"
                 : "=f"(v.x), "=f"(v.y), "=f"(v.z), "=f"(v.w) : "l"(p));
    return v;
}
__device__ __forceinline__ void stvol_f1(float* p, float a) {
    asm volatile("st.volatile.global.f32 [%0], %1;" :: "l"(p), "f"(a));
}

// ---------------- sentinel fill (fresh each graph replay) -------------------
__global__ void clear_h_kernel() {
    size_t i = (size_t)blockIdx.x * blockDim.x + threadIdx.x;   // uint4 index
    const unsigned s = SENTINEL;
    ((uint4*)g_h)[i] = make_uint4(s, s, s, s);
}

// ---------------- fp32 GEMM: C = (relu?)(A) @ B + bias, 128x128 / 8x8 ------
template <bool RELU_A>
__global__ void __launch_bounds__(256) gemm128_kernel(
    const float* __restrict__ A, const float* __restrict__ B,
    const float* __restrict__ bias, float* __restrict__ C,
    int M, int N, int K)
{
    __shared__ float As[8][128];   // As[k][m] (transposed)
    __shared__ float Bs[8][128];   // Bs[k][n]

    const int tid = threadIdx.x;
    const int bm = blockIdx.y << 7, bn = blockIdx.x << 7;

    const int arow = tid >> 1;             // 0..127
    const int acol = (tid & 1) << 2;       // 0 or 4
    const int brow = tid >> 5;             // 0..7
    const int bcol = (tid & 31) << 2;      // 0..124

    const float* Ap = A + (size_t)(bm + arow) * K + acol;
    const float* Bp = B + (size_t)brow * N + bn + bcol;

    const int tx = tid & 15, ty = tid >> 4;

    float acc[8][8];
#pragma unroll
    for (int i = 0; i < 8; i++)
#pragma unroll
        for (int j = 0; j < 8; j++) acc[i][j] = 0.f;

    float4 a4 = *(const float4*)Ap;
    float4 b4 = *(const float4*)Bp;

    for (int kb = 0; kb < K; kb += 8) {
        float4 av = a4, bv = b4;
        if (RELU_A) {
            av.x = fmaxf(av.x, 0.f); av.y = fmaxf(av.y, 0.f);
            av.z = fmaxf(av.z, 0.f); av.w = fmaxf(av.w, 0.f);
        }
        As[acol + 0][arow] = av.x;
        As[acol + 1][arow] = av.y;
        As[acol + 2][arow] = av.z;
        As[acol + 3][arow] = av.w;
        *(float4*)&Bs[brow][bcol] = bv;
        __syncthreads();

        if (kb + 8 < K) {                       // prefetch next k-slice
            a4 = *(const float4*)(Ap + kb + 8);
            b4 = *(const float4*)(Bp + (size_t)(kb + 8) * N);
        }

#pragma unroll
        for (int kk = 0; kk < 8; kk++) {
            float a8[8], b8[8];
            *(float4*)(a8)     = *(const float4*)&As[kk][ty << 3];
            *(float4*)(a8 + 4) = *(const float4*)&As[kk][(ty << 3) + 4];
            *(float4*)(b8)     = *(const float4*)&Bs[kk][tx << 3];
            *(float4*)(b8 + 4) = *(const float4*)&Bs[kk][(tx << 3) + 4];
#pragma unroll
            for (int i = 0; i < 8; i++)
#pragma unroll
                for (int j = 0; j < 8; j++)
                    acc[i][j] = fmaf(a8[i], b8[j], acc[i][j]);
        }
        __syncthreads();
    }

    float bb[8];
    *(float4*)(bb)     = *(const float4*)&bias[bn + (tx << 3)];
    *(float4*)(bb + 4) = *(const float4*)&bias[bn + (tx << 3) + 4];
#pragma unroll
    for (int i = 0; i < 8; i++) {
        float* Cp = C + (size_t)(bm + (ty << 3) + i) * N + bn + (tx << 3);
        *(float4*)(Cp)     = make_float4(acc[i][0] + bb[0], acc[i][1] + bb[1],
                                         acc[i][2] + bb[2], acc[i][3] + bb[3]);
        *(float4*)(Cp + 4) = make_float4(acc[i][4] + bb[4], acc[i][5] + bb[5],
                                         acc[i][6] + bb[6], acc[i][7] + bb[7]);
    }
}

// ---------------- persistent GRU recurrence ---------------------------------
// 128 CTAs x 256 threads. Warp w computes column cta*8+w; weights in registers.
// Sync: sentinel-in-band — h slot is ready iff it isn't the NaN sentinel.
// Each consumer thread polls exactly ONE float4 (4 KB row total).
__global__ void __launch_bounds__(256, 1) gru_recurrence_kernel(
    const float* __restrict__ Whr, const float* __restrict__ Whz,
    const float* __restrict__ Whn, const float* __restrict__ bhn,
    const float* __restrict__ init_state)
{
    __shared__ float sh_h[2][D_DIM];       // double buffer: h rows

    const int tid  = threadIdx.x;
    const int warp = tid >> 5, lane = tid & 31;
    const int col  = blockIdx.x * CPC + warp;

    // ---- one-time: weight slice into registers (48 packed f32x2 / gate) ----
    ull wr[16], wz[16], wn[16];
#pragma unroll
    for (int i = 0; i < 16; i++) {
        const int k0 = 2 * (lane + 32 * i);
        const size_t o0 = (size_t)k0 * D_DIM + col;
        const size_t o1 = (size_t)(k0 + 1) * D_DIM + col;
        wr[i] = pack2(Whr[o0], Whr[o1]);
        wz[i] = pack2(Whz[o0], Whz[o1]);
        wn[i] = pack2(Whn[o0], Whn[o1]);
    }
    const float bhn_c = bhn[col];

    float h_prev = init_state[col];
    float gr_c = g_Gr[col], gz_c = g_Gz[col], gn_c = g_Gn[col];

    for (int t = 0; t < T_LEN; t++) {
        float* dst = sh_h[t & 1];

        // ---- prefetch next step's gate pre-activations (independent) ----
        float grn = 0.f, gzn = 0.f, gnn = 0.f;
        if (lane == 0 && t + 1 < T_LEN) {
            const size_t o = (size_t)(t + 1) * D_DIM + col;
            grn = __ldg(&g_Gr[o]); gzn = __ldg(&g_Gz[o]); gnn = __ldg(&g_Gn[o]);
        }

        // ---- stage h_{t-1}: one float4 per thread, sentinel detection ----
        if (t == 0) {
            float4 v = ((const float4*)init_state)[tid];
            *(float4*)&dst[tid << 2] = v;
        } else {
            const float4* src = (const float4*)(g_h + (size_t)(t - 1) * D_DIM);
            float4 v = ldvol_f4(src + tid);
            while ((__float_as_uint(v.x) == SENTINEL) |
                   (__float_as_uint(v.y) == SENTINEL) |
                   (__float_as_uint(v.z) == SENTINEL) |
                   (__float_as_uint(v.w) == SENTINEL)) {
                v = ldvol_f4(src + tid);
            }
            *(float4*)&dst[tid << 2] = v;
        }
        __syncthreads();   // staging done; double buffer handles WAR

        // ---- packed dot products (3 gates, 2 accumulators each) ----
        const ull* h2 = (const ull*)dst;
        ull ar0 = 0, ar1 = 0, az0 = 0, az1 = 0, an0 = 0, an1 = 0;
#pragma unroll
        for (int i = 0; i < 16; i += 2) {
            ull h0 = h2[lane + 32 * i];
            ull h1 = h2[lane + 32 * (i + 1)];
            fma2(ar0, h0, wr[i]);  fma2(ar1, h1, wr[i + 1]);
            fma2(az0, h0, wz[i]);  fma2(az1, h1, wz[i + 1]);
            fma2(an0, h0, wn[i]);  fma2(an1, h1, wn[i + 1]);
        }
        float lo, hi, ar, az, an;
        unpack2(ar0, lo, hi); ar = lo + hi; unpack2(ar1, lo, hi); ar += lo + hi;
        unpack2(az0, lo, hi); az = lo + hi; unpack2(az1, lo, hi); az += lo + hi;
        unpack2(an0, lo, hi); an = lo + hi; unpack2(an1, lo, hi); an += lo + hi;

#pragma unroll
        for (int o = 16; o > 0; o >>= 1) {
            ar += __shfl_xor_sync(0xFFFFFFFFu, ar, o);
            az += __shfl_xor_sync(0xFFFFFFFFu, az, o);
            an += __shfl_xor_sync(0xFFFFFFFFu, an, o);
        }

        // ---- gate math + single publish store (lane 0 of each warp) ----
        if (lane == 0) {
            float er = __expf(-(gr_c + ar));
            float r  = __fdividef(1.f, 1.f + er);
            float ez = __expf(-(gz_c + az));
            float z  = __fdividef(1.f, 1.f + ez);
            float nx = gn_c + r * (an + bhn_c);
            float en = __expf(-2.f * nx);
            float n  = __fdividef(1.f - en, 1.f + en);      // tanh(nx)
            float hnew = n + z * (h_prev - n);
            stvol_f1(g_h + (size_t)t * D_DIM + col, hnew);
            h_prev = hnew;
            gr_c = grn; gz_c = gzn; gn_c = gnn;
        }
    }
}

// ---------------- residual + layernorm (in-place on d_out) -----------------
__global__ void __launch_bounds__(256) layernorm_kernel(
    const float* __restrict__ xs, const float* __restrict__ ln_scale,
    const float* __restrict__ ln_bias, float* __restrict__ inout)
{
    __shared__ float red0[8], red1[8];
    const int t = blockIdx.x, tid = threadIdx.x;
    const float* xrow = xs + (size_t)t * D_DIM;
    float* yrow = inout + (size_t)t * D_DIM;

    float v[4];
    float s = 0.f, s2 = 0.f;
#pragma unroll
    for (int i = 0; i < 4; i++) {
        int idx = tid + i * 256;
        float y = xrow[idx] + yrow[idx];
        v[i] = y; s += y; s2 += y * y;
    }
#pragma unroll
    for (int o = 16; o > 0; o >>= 1) {
        s  += __shfl_xor_sync(0xFFFFFFFFu, s,  o);
        s2 += __shfl_xor_sync(0xFFFFFFFFu, s2, o);
    }
    const int warp = tid >> 5, lane = tid & 31;
    if (lane == 0) { red0[warp] = s; red1[warp] = s2; }
    __syncthreads();
    if (warp == 0) {
        float a = (lane < 8) ? red0[lane] : 0.f;
        float b = (lane < 8) ? red1[lane] : 0.f;
#pragma unroll
        for (int o = 4; o > 0; o >>= 1) {
            a += __shfl_xor_sync(0xFFFFFFFFu, a, o);
            b += __shfl_xor_sync(0xFFFFFFFFu, b, o);
        }
        if (lane == 0) { red0[0] = a; red1[0] = b; }
    }
    __syncthreads();

    const float mu   = red0[0] * (1.f / D_DIM);
    const float var  = red1[0] * (1.f / D_DIM) - mu * mu;
    const float rstd = rsqrtf(var + 1e-6f);
#pragma unroll
    for (int i = 0; i < 4; i++) {
        int idx = tid + i * 256;
        yrow[idx] = (v[i] - mu) * rstd * ln_scale[idx] + ln_bias[idx];
    }
}

// ---------------- launcher --------------------------------------------------
extern "C" void kernel_launch(void* const* d_in, const int* in_sizes, int n_in,
                              void* d_out, int out_size)
{
    const float* xs        = (const float*)d_in[0];
    const float* init_st   = (const float*)d_in[1];
    const float* Wir       = (const float*)d_in[2];
    const float* Wiz       = (const float*)d_in[3];
    const float* Win       = (const float*)d_in[4];
    const float* bir       = (const float*)d_in[5];
    const float* biz       = (const float*)d_in[6];
    const float* bin_      = (const float*)d_in[7];
    const float* Whr       = (const float*)d_in[8];
    const float* Whz       = (const float*)d_in[9];
    const float* Whn       = (const float*)d_in[10];
    const float* bhn       = (const float*)d_in[11];
    const float* Wl        = (const float*)d_in[12];
    const float* bl        = (const float*)d_in[13];
    const float* ln_scale  = (const float*)d_in[14];
    const float* ln_bias   = (const float*)d_in[15];
    float* out = (float*)d_out;

    void *pGr, *pGz, *pGn, *pH;
    cudaGetSymbolAddress(&pGr, g_Gr);
    cudaGetSymbolAddress(&pGz, g_Gz);
    cudaGetSymbolAddress(&pGn, g_Gn);
    cudaGetSymbolAddress(&pH,  g_h);

    dim3 gemm_grid(D_DIM / 128, T_LEN / 128);   // (8, 32)

    // 1) fill h history with sentinel (graph-replay determinism)
    clear_h_kernel<<<(T_LEN * D_DIM / 4) / 256, 256>>>();

    // 2) input-side gate pre-GEMMs (parallel over time)
    gemm128_kernel<false><<<gemm_grid, 256>>>(xs, Wir, bir, (float*)pGr,
                                              T_LEN, D_DIM, D_DIM);
    gemm128_kernel<false><<<gemm_grid, 256>>>(xs, Wiz, biz, (float*)pGz,
                                              T_LEN, D_DIM, D_DIM);
    gemm128_kernel<false><<<gemm_grid, 256>>>(xs, Win, bin_, (float*)pGn,
                                              T_LEN, D_DIM, D_DIM);

    // 3) sequential recurrence: persistent grid, register-resident weights
    gru_recurrence_kernel<<<NCTA, 256>>>(Whr, Whz, Whn, bhn, init_st);

    // 4) post dense: d_out = relu(h) @ Wl + bl
    gemm128_kernel<true><<<gemm_grid, 256>>>((const float*)pH, Wl, bl, out,
                                             T_LEN, D_DIM, D_DIM);

    // 5) residual + layernorm in-place on d_out
    layernorm_kernel<<<T_LEN, 256>>>(xs, ln_scale, ln_bias, out);
}

// round 9
// speedup vs baseline: 1.5704x; 1.1073x over previous
#include <cuda_runtime.h>

#define T_LEN 4096
#define D_DIM 1024
#define NCTA  128
#define CPC   8      // columns per CTA (= warps per CTA)

typedef unsigned long long ull;

// ---------------- scratch (device globals: no allocation allowed) -----------
__device__ float  g_Gr[T_LEN * D_DIM];
__device__ float  g_Gz[T_LEN * D_DIM];
__device__ float  g_Gn[T_LEN * D_DIM];
__device__ float2 g_hs[T_LEN * D_DIM];   // {h, step_tag}; also h-history for GEMM

// ---------------- PTX helpers ----------------------------------------------
__device__ __forceinline__ ull pack2(float lo, float hi) {
    ull r;
    asm("mov.b64 %0, {%1, %2};" : "=l"(r) : "f"(lo), "f"(hi));
    return r;
}
__device__ __forceinline__ void unpack2(ull v, float& lo, float& hi) {
    asm("mov.b64 {%0, %1}, %2;" : "=f"(lo), "=f"(hi) : "l"(v));
}
__device__ __forceinline__ void fma2(ull& d, ull a, ull b) {
    asm("fma.rn.f32x2 %0, %1, %2, %0;" : "+l"(d) : "l"(a), "l"(b));
}
__device__ __forceinline__ float4 ldvol_f4(const float4* p) {
    float4 v;
    asm volatile("ld.volatile.global.v4.f32 {%0,%1,%2,%3}, [%4];"
                 : "=f"(v.x), "=f"(v.y), "=f"(v.z), "=f"(v.w) : "l"(p));
    return v;
}
__device__ __forceinline__ void stvol_f2(float2* p, float a, float b) {
    asm volatile("st.volatile.global.v2.f32 [%0], {%1,%2};" :: "l"(p), "f"(a), "f"(b));
}

// ---------------- tag clear (fresh each graph replay) -----------------------
__global__ void clear_tags_kernel() {
    size_t i = (size_t)blockIdx.x * blockDim.x + threadIdx.x;   // float4 index
    ((float4*)g_hs)[i] = make_float4(0.f, 0.f, 0.f, 0.f);
}

// ---------------- fp32 GEMM: C = (relu?)(A) @ B + bias, 128x128 / 8x8 ------
// STRIDED_A: A element (m,k) lives at A[2*(m*K+k)] (interleaved {h,tag} buffer)
template <bool RELU_A, bool STRIDED_A>
__global__ void __launch_bounds__(256) gemm128_kernel(
    const float* __restrict__ A, const float* __restrict__ B,
    const float* __restrict__ bias, float* __restrict__ C,
    int M, int N, int K)
{
    __shared__ float As[8][128];   // As[k][m] (transposed)
    __shared__ float Bs[8][128];   // Bs[k][n]

    const int tid = threadIdx.x;
    const int bm = blockIdx.y << 7, bn = blockIdx.x << 7;

    const int arow = tid >> 1;             // 0..127
    const int acol = (tid & 1) << 2;       // 0 or 4
    const int brow = tid >> 5;             // 0..7
    const int bcol = (tid & 31) << 2;      // 0..124

    const float* Bp = B + (size_t)brow * N + bn + bcol;
    const size_t a_elem0 = (size_t)(bm + arow) * K + acol;

    const int tx = tid & 15, ty = tid >> 4;

    float acc[8][8];
#pragma unroll
    for (int i = 0; i < 8; i++)
#pragma unroll
        for (int j = 0; j < 8; j++) acc[i][j] = 0.f;

    auto load_a = [&](int kb) -> float4 {
        if (STRIDED_A) {
            const float4* p = (const float4*)(A + 2 * (a_elem0 + kb));
            float4 u = p[0], v = p[1];
            return make_float4(u.x, u.z, v.x, v.z);
        } else {
            return *(const float4*)(A + a_elem0 + kb);
        }
    };

    float4 a4 = load_a(0);
    float4 b4 = *(const float4*)Bp;

    for (int kb = 0; kb < K; kb += 8) {
        float4 av = a4, bv = b4;
        if (RELU_A) {
            av.x = fmaxf(av.x, 0.f); av.y = fmaxf(av.y, 0.f);
            av.z = fmaxf(av.z, 0.f); av.w = fmaxf(av.w, 0.f);
        }
        As[acol + 0][arow] = av.x;
        As[acol + 1][arow] = av.y;
        As[acol + 2][arow] = av.z;
        As[acol + 3][arow] = av.w;
        *(float4*)&Bs[brow][bcol] = bv;
        __syncthreads();

        if (kb + 8 < K) {                       // prefetch next k-slice
            a4 = load_a(kb + 8);
            b4 = *(const float4*)(Bp + (size_t)(kb + 8) * N);
        }

#pragma unroll
        for (int kk = 0; kk < 8; kk++) {
            float a8[8], b8[8];
            *(float4*)(a8)     = *(const float4*)&As[kk][ty << 3];
            *(float4*)(a8 + 4) = *(const float4*)&As[kk][(ty << 3) + 4];
            *(float4*)(b8)     = *(const float4*)&Bs[kk][tx << 3];
            *(float4*)(b8 + 4) = *(const float4*)&Bs[kk][(tx << 3) + 4];
#pragma unroll
            for (int i = 0; i < 8; i++)
#pragma unroll
                for (int j = 0; j < 8; j++)
                    acc[i][j] = fmaf(a8[i], b8[j], acc[i][j]);
        }
        __syncthreads();
    }

    float bb[8];
    *(float4*)(bb)     = *(const float4*)&bias[bn + (tx << 3)];
    *(float4*)(bb + 4) = *(const float4*)&bias[bn + (tx << 3) + 4];
#pragma unroll
    for (int i = 0; i < 8; i++) {
        float* Cp = C + (size_t)(bm + (ty << 3) + i) * N + bn + (tx << 3);
        *(float4*)(Cp)     = make_float4(acc[i][0] + bb[0], acc[i][1] + bb[1],
                                         acc[i][2] + bb[2], acc[i][3] + bb[3]);
        *(float4*)(Cp + 4) = make_float4(acc[i][4] + bb[4], acc[i][5] + bb[5],
                                         acc[i][6] + bb[6], acc[i][7] + bb[7]);
    }
}

// ---------------- persistent GRU recurrence (R2 transport, trimmed) ---------
// 128 CTAs x 256 threads. Warp w owns column cta*8+w; weights in registers.
// Dual-slot fused {h,tag} polling, double-buffered smem h, one bar per step.
// Changes vs measured-best R2: single publish store; z-gate on lane 1.
__global__ void __launch_bounds__(256, 1) gru_recurrence_kernel(
    const float* __restrict__ Whr, const float* __restrict__ Whz,
    const float* __restrict__ Whn, const float* __restrict__ bhn,
    const float* __restrict__ init_state)
{
    __shared__ float sh_h[2][D_DIM];       // double buffer: h rows

    const int tid  = threadIdx.x;
    const int warp = tid >> 5, lane = tid & 31;
    const int col  = blockIdx.x * CPC + warp;

    // ---- one-time: weight slice into registers (48 packed f32x2 / gate) ----
    ull wr[16], wz[16], wn[16];
#pragma unroll
    for (int i = 0; i < 16; i++) {
        const int k0 = 2 * (lane + 32 * i);
        const size_t o0 = (size_t)k0 * D_DIM + col;
        const size_t o1 = (size_t)(k0 + 1) * D_DIM + col;
        wr[i] = pack2(Whr[o0], Whr[o1]);
        wz[i] = pack2(Whz[o0], Whz[o1]);
        wn[i] = pack2(Whn[o0], Whn[o1]);
    }
    const float bhn_c = bhn[col];

    float h_prev = init_state[col];
    // lane 0 carries gr/gn prefetch, lane 1 carries gz prefetch
    float gr_c = 0.f, gz_c = 0.f, gn_c = 0.f;
    if (lane == 0) { gr_c = g_Gr[col]; gn_c = g_Gn[col]; }
    if (lane == 1) { gz_c = g_Gz[col]; }

    for (int t = 0; t < T_LEN; t++) {
        float* dst = sh_h[t & 1];

        // ---- prefetch next step's gate pre-activations ----
        float grn = 0.f, gzn = 0.f, gnn = 0.f;
        if (t + 1 < T_LEN) {
            const size_t o = (size_t)(t + 1) * D_DIM + col;
            if (lane == 0) { grn = __ldg(&g_Gr[o]); gnn = __ldg(&g_Gn[o]); }
            if (lane == 1) { gzn = __ldg(&g_Gz[o]); }
        }

        // ---- stage h_{t-1} (concurrent dual-slot poll, as R2) ----
        if (t == 0) {
            float4 v = ((const float4*)init_state)[tid];
            *(float4*)&dst[tid << 2] = v;
        } else {
            const float4* src = (const float4*)(g_hs + (size_t)(t - 1) * D_DIM);
            const unsigned tag = __float_as_uint((float)t);
            float4 a = ldvol_f4(src + tid);
            float4 b = ldvol_f4(src + tid + 256);
            bool da = false, db = false;
            while (true) {
                if (!da && __float_as_uint(a.y) == tag && __float_as_uint(a.w) == tag) {
                    ((float2*)dst)[tid] = make_float2(a.x, a.z);
                    da = true;
                }
                if (!db && __float_as_uint(b.y) == tag && __float_as_uint(b.w) == tag) {
                    ((float2*)dst)[tid + 256] = make_float2(b.x, b.z);
                    db = true;
                }
                if (da && db) break;
                if (!da) a = ldvol_f4(src + tid);
                if (!db) b = ldvol_f4(src + tid + 256);
            }
        }
        __syncthreads();   // staging done; double buffer handles WAR

        // ---- packed dot products (3 gates, 2 accumulators each) ----
        const ull* h2 = (const ull*)dst;
        ull ar0 = 0, ar1 = 0, az0 = 0, az1 = 0, an0 = 0, an1 = 0;
#pragma unroll
        for (int i = 0; i < 16; i += 2) {
            ull h0 = h2[lane + 32 * i];
            ull h1 = h2[lane + 32 * (i + 1)];
            fma2(ar0, h0, wr[i]);  fma2(ar1, h1, wr[i + 1]);
            fma2(az0, h0, wz[i]);  fma2(az1, h1, wz[i + 1]);
            fma2(an0, h0, wn[i]);  fma2(an1, h1, wn[i + 1]);
        }
        float lo, hi, ar, az, an;
        unpack2(ar0, lo, hi); ar = lo + hi; unpack2(ar1, lo, hi); ar += lo + hi;
        unpack2(az0, lo, hi); az = lo + hi; unpack2(az1, lo, hi); az += lo + hi;
        unpack2(an0, lo, hi); an = lo + hi; unpack2(an1, lo, hi); an += lo + hi;

#pragma unroll
        for (int o = 16; o > 0; o >>= 1) {
            ar += __shfl_xor_sync(0xFFFFFFFFu, ar, o);
            az += __shfl_xor_sync(0xFFFFFFFFu, az, o);
            an += __shfl_xor_sync(0xFFFFFFFFu, an, o);
        }
        // butterfly leaves sums on ALL lanes: lane 1 computes z concurrently
        float z1 = 0.f;
        if (lane == 1) {
            float ez = __expf(-(gz_c + az));
            z1 = __fdividef(1.f, 1.f + ez);
            gz_c = gzn;
        }
        float z = __shfl_sync(0xFFFFFFFFu, z1, 1);

        // ---- serial r -> n chain + single publish store (lane 0) ----
        if (lane == 0) {
            float er = __expf(-(gr_c + ar));
            float r  = __fdividef(1.f, 1.f + er);
            float nx = gn_c + r * (an + bhn_c);
            float en = __expf(-2.f * nx);
            float n  = __fdividef(1.f - en, 1.f + en);      // tanh(nx)
            float hnew = n + z * (h_prev - n);
            stvol_f2(g_hs + (size_t)t * D_DIM + col, hnew, (float)(t + 1));
            h_prev = hnew;
            gr_c = grn; gn_c = gnn;
        }
    }
}

// ---------------- residual + layernorm (in-place on d_out) -----------------
__global__ void __launch_bounds__(256) layernorm_kernel(
    const float* __restrict__ xs, const float* __restrict__ ln_scale,
    const float* __restrict__ ln_bias, float* __restrict__ inout)
{
    __shared__ float red0[8], red1[8];
    const int t = blockIdx.x, tid = threadIdx.x;
    const float* xrow = xs + (size_t)t * D_DIM;
    float* yrow = inout + (size_t)t * D_DIM;

    float v[4];
    float s = 0.f, s2 = 0.f;
#pragma unroll
    for (int i = 0; i < 4; i++) {
        int idx = tid + i * 256;
        float y = xrow[idx] + yrow[idx];
        v[i] = y; s += y; s2 += y * y;
    }
#pragma unroll
    for (int o = 16; o > 0; o >>= 1) {
        s  += __shfl_xor_sync(0xFFFFFFFFu, s,  o);
        s2 += __shfl_xor_sync(0xFFFFFFFFu, s2, o);
    }
    const int warp = tid >> 5, lane = tid & 31;
    if (lane == 0) { red0[warp] = s; red1[warp] = s2; }
    __syncthreads();
    if (warp == 0) {
        float a = (lane < 8) ? red0[lane] : 0.f;
        float b = (lane < 8) ? red1[lane] : 0.f;
#pragma unroll
        for (int o = 4; o > 0; o >>= 1) {
            a += __shfl_xor_sync(0xFFFFFFFFu, a, o);
            b += __shfl_xor_sync(0xFFFFFFFFu, b, o);
        }
        if (lane == 0) { red0[0] = a; red1[0] = b; }
    }
    __syncthreads();

    const float mu   = red0[0] * (1.f / D_DIM);
    const float var  = red1[0] * (1.f / D_DIM) - mu * mu;
    const float rstd = rsqrtf(var + 1e-6f);
#pragma unroll
    for (int i = 0; i < 4; i++) {
        int idx = tid + i * 256;
        yrow[idx] = (v[i] - mu) * rstd * ln_scale[idx] + ln_bias[idx];
    }
}

// ---------------- launcher --------------------------------------------------
extern "C" void kernel_launch(void* const* d_in, const int* in_sizes, int n_in,
                              void* d_out, int out_size)
{
    const float* xs        = (const float*)d_in[0];
    const float* init_st   = (const float*)d_in[1];
    const float* Wir       = (const float*)d_in[2];
    const float* Wiz       = (const float*)d_in[3];
    const float* Win       = (const float*)d_in[4];
    const float* bir       = (const float*)d_in[5];
    const float* biz       = (const float*)d_in[6];
    const float* bin_      = (const float*)d_in[7];
    const float* Whr       = (const float*)d_in[8];
    const float* Whz       = (const float*)d_in[9];
    const float* Whn       = (const float*)d_in[10];
    const float* bhn       = (const float*)d_in[11];
    const float* Wl        = (const float*)d_in[12];
    const float* bl        = (const float*)d_in[13];
    const float* ln_scale  = (const float*)d_in[14];
    const float* ln_bias   = (const float*)d_in[15];
    float* out = (float*)d_out;

    void *pGr, *pGz, *pGn, *pHs;
    cudaGetSymbolAddress(&pGr, g_Gr);
    cudaGetSymbolAddress(&pGz, g_Gz);
    cudaGetSymbolAddress(&pGn, g_Gn);
    cudaGetSymbolAddress(&pHs, g_hs);

    dim3 gemm_grid(D_DIM / 128, T_LEN / 128);   // (8, 32)

    // 1) clear h tags (graph-replay determinism)
    clear_tags_kernel<<<(T_LEN * D_DIM * 2 / 4) / 256, 256>>>();

    // 2) input-side gate pre-GEMMs (parallel over time)
    gemm128_kernel<false, false><<<gemm_grid, 256>>>(xs, Wir, bir, (float*)pGr,
                                                     T_LEN, D_DIM, D_DIM);
    gemm128_kernel<false, false><<<gemm_grid, 256>>>(xs, Wiz, biz, (float*)pGz,
                                                     T_LEN, D_DIM, D_DIM);
    gemm128_kernel<false, false><<<gemm_grid, 256>>>(xs, Win, bin_, (float*)pGn,
                                                     T_LEN, D_DIM, D_DIM);

    // 3) sequential recurrence: persistent grid, register-resident weights
    gru_recurrence_kernel<<<NCTA, 256>>>(Whr, Whz, Whn, bhn, init_st);

    // 4) post dense: d_out = relu(h) @ Wl + bl  (h read strided from g_hs)
    gemm128_kernel<true, true><<<gemm_grid, 256>>>((const float*)pHs, Wl, bl,
                                                   out, T_LEN, D_DIM, D_DIM);

    // 5) residual + layernorm in-place on d_out
    layernorm_kernel<<<T_LEN, 256>>>(xs, ln_scale, ln_bias, out);
}

// round 10
// speedup vs baseline: 1.7119x; 1.0901x over previous
#include <cuda_runtime.h>

#define T_LEN 4096
#define D_DIM 1024
#define NCTA  128
#define CPC   8      // columns per CTA (= warps per CTA)

typedef unsigned long long ull;

// ---------------- scratch (device globals: no allocation allowed) -----------
__device__ float    g_Gr[T_LEN * D_DIM];
__device__ float    g_Gz[T_LEN * D_DIM];
__device__ float    g_Gn[T_LEN * D_DIM];
__device__ float    g_h [T_LEN * D_DIM];   // plain h history
__device__ unsigned g_cnt[T_LEN];          // per-step arrival counter

// ---------------- PTX helpers ----------------------------------------------
__device__ __forceinline__ ull pack2(float lo, float hi) {
    ull r;
    asm("mov.b64 %0, {%1, %2};" : "=l"(r) : "f"(lo), "f"(hi));
    return r;
}
__device__ __forceinline__ void unpack2(ull v, float& lo, float& hi) {
    asm("mov.b64 {%0, %1}, %2;" : "=f"(lo), "=f"(hi) : "l"(v));
}
__device__ __forceinline__ void fma2(ull& d, ull a, ull b) {
    asm("fma.rn.f32x2 %0, %1, %2, %0;" : "+l"(d) : "l"(a), "l"(b));
}
__device__ __forceinline__ unsigned ld_acquire(const unsigned* p) {
    unsigned v;
    asm volatile("ld.acquire.gpu.u32 %0, [%1];" : "=r"(v) : "l"(p));
    return v;
}

// ---------------- counter clear (fresh each graph replay) -------------------
__global__ void clear_cnt_kernel() {
    int i = blockIdx.x * blockDim.x + threadIdx.x;
    if (i < T_LEN) g_cnt[i] = 0u;
}

// ---------------- fp32 GEMM: C = (relu?)(A) @ B + bias, 128x128 / 8x8 ------
template <bool RELU_A>
__global__ void __launch_bounds__(256) gemm128_kernel(
    const float* __restrict__ A, const float* __restrict__ B,
    const float* __restrict__ bias, float* __restrict__ C,
    int M, int N, int K)
{
    __shared__ float As[8][128];   // As[k][m] (transposed)
    __shared__ float Bs[8][128];   // Bs[k][n]

    const int tid = threadIdx.x;
    const int bm = blockIdx.y << 7, bn = blockIdx.x << 7;

    const int arow = tid >> 1;             // 0..127
    const int acol = (tid & 1) << 2;       // 0 or 4
    const int brow = tid >> 5;             // 0..7
    const int bcol = (tid & 31) << 2;      // 0..124

    const float* Ap = A + (size_t)(bm + arow) * K + acol;
    const float* Bp = B + (size_t)brow * N + bn + bcol;

    const int tx = tid & 15, ty = tid >> 4;

    float acc[8][8];
#pragma unroll
    for (int i = 0; i < 8; i++)
#pragma unroll
        for (int j = 0; j < 8; j++) acc[i][j] = 0.f;

    float4 a4 = *(const float4*)Ap;
    float4 b4 = *(const float4*)Bp;

    for (int kb = 0; kb < K; kb += 8) {
        float4 av = a4, bv = b4;
        if (RELU_A) {
            av.x = fmaxf(av.x, 0.f); av.y = fmaxf(av.y, 0.f);
            av.z = fmaxf(av.z, 0.f); av.w = fmaxf(av.w, 0.f);
        }
        As[acol + 0][arow] = av.x;
        As[acol + 1][arow] = av.y;
        As[acol + 2][arow] = av.z;
        As[acol + 3][arow] = av.w;
        *(float4*)&Bs[brow][bcol] = bv;
        __syncthreads();

        if (kb + 8 < K) {                       // prefetch next k-slice
            a4 = *(const float4*)(Ap + kb + 8);
            b4 = *(const float4*)(Bp + (size_t)(kb + 8) * N);
        }

#pragma unroll
        for (int kk = 0; kk < 8; kk++) {
            float a8[8], b8[8];
            *(float4*)(a8)     = *(const float4*)&As[kk][ty << 3];
            *(float4*)(a8 + 4) = *(const float4*)&As[kk][(ty << 3) + 4];
            *(float4*)(b8)     = *(const float4*)&Bs[kk][tx << 3];
            *(float4*)(b8 + 4) = *(const float4*)&Bs[kk][(tx << 3) + 4];
#pragma unroll
            for (int i = 0; i < 8; i++)
#pragma unroll
                for (int j = 0; j < 8; j++)
                    acc[i][j] = fmaf(a8[i], b8[j], acc[i][j]);
        }
        __syncthreads();
    }

    float bb[8];
    *(float4*)(bb)     = *(const float4*)&bias[bn + (tx << 3)];
    *(float4*)(bb + 4) = *(const float4*)&bias[bn + (tx << 3) + 4];
#pragma unroll
    for (int i = 0; i < 8; i++) {
        float* Cp = C + (size_t)(bm + (ty << 3) + i) * N + bn + (tx << 3);
        *(float4*)(Cp)     = make_float4(acc[i][0] + bb[0], acc[i][1] + bb[1],
                                         acc[i][2] + bb[2], acc[i][3] + bb[3]);
        *(float4*)(Cp + 4) = make_float4(acc[i][4] + bb[4], acc[i][5] + bb[5],
                                         acc[i][6] + bb[6], acc[i][7] + bb[7]);
    }
}

// ---------------- persistent GRU recurrence ---------------------------------
// 128 CTAs x 256 threads. Warp w owns column cta*8+w; weights in registers.
// Barrier: single counter per step. ONE polled cache line chip-wide; h row
// is read once, coalesced, at unloaded L2 latency after the barrier passes.
__global__ void __launch_bounds__(256, 1) gru_recurrence_kernel(
    const float* __restrict__ Whr, const float* __restrict__ Whz,
    const float* __restrict__ Whn, const float* __restrict__ bhn,
    const float* __restrict__ init_state)
{
    __shared__ float sh_h[2][D_DIM];       // double buffer: h rows

    const int tid  = threadIdx.x;
    const int warp = tid >> 5, lane = tid & 31;
    const int col  = blockIdx.x * CPC + warp;

    // ---- one-time: weight slice into registers (48 packed f32x2 / gate) ----
    ull wr[16], wz[16], wn[16];
#pragma unroll
    for (int i = 0; i < 16; i++) {
        const int k0 = 2 * (lane + 32 * i);
        const size_t o0 = (size_t)k0 * D_DIM + col;
        const size_t o1 = (size_t)(k0 + 1) * D_DIM + col;
        wr[i] = pack2(Whr[o0], Whr[o1]);
        wz[i] = pack2(Whz[o0], Whz[o1]);
        wn[i] = pack2(Whn[o0], Whn[o1]);
    }
    const float bhn_c = bhn[col];

    float h_prev = init_state[col];
    float gr_c = g_Gr[col], gz_c = g_Gz[col], gn_c = g_Gn[col];

    for (int t = 0; t < T_LEN; t++) {
        float* dst = sh_h[t & 1];

        // ---- wait for step t-1 completion (tid0 polls ONE line) ----
        if (t > 0) {
            if (tid == 0) {
                while (ld_acquire(&g_cnt[t - 1]) < (unsigned)NCTA) {}
            }
            __syncthreads();               // release the CTA to read row t-1
        }

        // ---- prefetch next step's gate pre-activations ----
        float grn = 0.f, gzn = 0.f, gnn = 0.f;
        if (lane == 0 && t + 1 < T_LEN) {
            const size_t o = (size_t)(t + 1) * D_DIM + col;
            grn = __ldg(&g_Gr[o]); gzn = __ldg(&g_Gz[o]); gnn = __ldg(&g_Gn[o]);
        }

        // ---- one-shot coalesced stage of h_{t-1} into smem ----
        if (t == 0) {
            float4 v = ((const float4*)init_state)[tid];
            *(float4*)&dst[tid << 2] = v;
        } else {
            const float4* src = (const float4*)(g_h + (size_t)(t - 1) * D_DIM);
            float4 v = src[tid];           // plain load: first touch post-acquire
            *(float4*)&dst[tid << 2] = v;
        }
        __syncthreads();                   // staging complete

        // ---- packed dot products (3 gates, 2 accumulators each) ----
        const ull* h2 = (const ull*)dst;
        ull ar0 = 0, ar1 = 0, az0 = 0, az1 = 0, an0 = 0, an1 = 0;
#pragma unroll
        for (int i = 0; i < 16; i += 2) {
            ull h0 = h2[lane + 32 * i];
            ull h1 = h2[lane + 32 * (i + 1)];
            fma2(ar0, h0, wr[i]);  fma2(ar1, h1, wr[i + 1]);
            fma2(az0, h0, wz[i]);  fma2(az1, h1, wz[i + 1]);
            fma2(an0, h0, wn[i]);  fma2(an1, h1, wn[i + 1]);
        }
        float lo, hi, ar, az, an;
        unpack2(ar0, lo, hi); ar = lo + hi; unpack2(ar1, lo, hi); ar += lo + hi;
        unpack2(az0, lo, hi); az = lo + hi; unpack2(az1, lo, hi); az += lo + hi;
        unpack2(an0, lo, hi); an = lo + hi; unpack2(an1, lo, hi); an += lo + hi;

#pragma unroll
        for (int o = 16; o > 0; o >>= 1) {
            ar += __shfl_xor_sync(0xFFFFFFFFu, ar, o);
            az += __shfl_xor_sync(0xFFFFFFFFu, az, o);
            an += __shfl_xor_sync(0xFFFFFFFFu, an, o);
        }

        // ---- gate math + publish (lane 0 of each warp) ----
        if (lane == 0) {
            float er = __expf(-(gr_c + ar));
            float r  = __fdividef(1.f, 1.f + er);
            float ez = __expf(-(gz_c + az));
            float z  = __fdividef(1.f, 1.f + ez);
            float nx = gn_c + r * (an + bhn_c);
            float en = __expf(-2.f * nx);
            float n  = __fdividef(1.f - en, 1.f + en);      // tanh(nx)
            float hnew = n + z * (h_prev - n);
            g_h[(size_t)t * D_DIM + col] = hnew;
            __threadfence();               // h store visible before arrive
            h_prev = hnew;
            gr_c = grn; gz_c = gzn; gn_c = gnn;
        }
        __syncthreads();                   // all 8 column stores fenced

        if (tid == 0) atomicAdd(&g_cnt[t], 1u);   // arrive
    }
}

// ---------------- residual + layernorm (in-place on d_out) -----------------
__global__ void __launch_bounds__(256) layernorm_kernel(
    const float* __restrict__ xs, const float* __restrict__ ln_scale,
    const float* __restrict__ ln_bias, float* __restrict__ inout)
{
    __shared__ float red0[8], red1[8];
    const int t = blockIdx.x, tid = threadIdx.x;
    const float* xrow = xs + (size_t)t * D_DIM;
    float* yrow = inout + (size_t)t * D_DIM;

    float v[4];
    float s = 0.f, s2 = 0.f;
#pragma unroll
    for (int i = 0; i < 4; i++) {
        int idx = tid + i * 256;
        float y = xrow[idx] + yrow[idx];
        v[i] = y; s += y; s2 += y * y;
    }
#pragma unroll
    for (int o = 16; o > 0; o >>= 1) {
        s  += __shfl_xor_sync(0xFFFFFFFFu, s,  o);
        s2 += __shfl_xor_sync(0xFFFFFFFFu, s2, o);
    }
    const int warp = tid >> 5, lane = tid & 31;
    if (lane == 0) { red0[warp] = s; red1[warp] = s2; }
    __syncthreads();
    if (warp == 0) {
        float a = (lane < 8) ? red0[lane] : 0.f;
        float b = (lane < 8) ? red1[lane] : 0.f;
#pragma unroll
        for (int o = 4; o > 0; o >>= 1) {
            a += __shfl_xor_sync(0xFFFFFFFFu, a, o);
            b += __shfl_xor_sync(0xFFFFFFFFu, b, o);
        }
        if (lane == 0) { red0[0] = a; red1[0] = b; }
    }
    __syncthreads();

    const float mu   = red0[0] * (1.f / D_DIM);
    const float var  = red1[0] * (1.f / D_DIM) - mu * mu;
    const float rstd = rsqrtf(var + 1e-6f);
#pragma unroll
    for (int i = 0; i < 4; i++) {
        int idx = tid + i * 256;
        yrow[idx] = (v[i] - mu) * rstd * ln_scale[idx] + ln_bias[idx];
    }
}

// ---------------- launcher --------------------------------------------------
extern "C" void kernel_launch(void* const* d_in, const int* in_sizes, int n_in,
                              void* d_out, int out_size)
{
    const float* xs        = (const float*)d_in[0];
    const float* init_st   = (const float*)d_in[1];
    const float* Wir       = (const float*)d_in[2];
    const float* Wiz       = (const float*)d_in[3];
    const float* Win       = (const float*)d_in[4];
    const float* bir       = (const float*)d_in[5];
    const float* biz       = (const float*)d_in[6];
    const float* bin_      = (const float*)d_in[7];
    const float* Whr       = (const float*)d_in[8];
    const float* Whz       = (const float*)d_in[9];
    const float* Whn       = (const float*)d_in[10];
    const float* bhn       = (const float*)d_in[11];
    const float* Wl        = (const float*)d_in[12];
    const float* bl        = (const float*)d_in[13];
    const float* ln_scale  = (const float*)d_in[14];
    const float* ln_bias   = (const float*)d_in[15];
    float* out = (float*)d_out;

    void *pGr, *pGz, *pGn, *pH;
    cudaGetSymbolAddress(&pGr, g_Gr);
    cudaGetSymbolAddress(&pGz, g_Gz);
    cudaGetSymbolAddress(&pGn, g_Gn);
    cudaGetSymbolAddress(&pH,  g_h);

    dim3 gemm_grid(D_DIM / 128, T_LEN / 128);   // (8, 32)

    // 1) clear per-step arrival counters (graph-replay determinism)
    clear_cnt_kernel<<<(T_LEN + 255) / 256, 256>>>();

    // 2) input-side gate pre-GEMMs (parallel over time)
    gemm128_kernel<false><<<gemm_grid, 256>>>(xs, Wir, bir, (float*)pGr,
                                              T_LEN, D_DIM, D_DIM);
    gemm128_kernel<false><<<gemm_grid, 256>>>(xs, Wiz, biz, (float*)pGz,
                                              T_LEN, D_DIM, D_DIM);
    gemm128_kernel<false><<<gemm_grid, 256>>>(xs, Win, bin_, (float*)pGn,
                                              T_LEN, D_DIM, D_DIM);

    // 3) sequential recurrence: persistent grid, register-resident weights
    gru_recurrence_kernel<<<NCTA, 256>>>(Whr, Whz, Whn, bhn, init_st);

    // 4) post dense: d_out = relu(h) @ Wl + bl
    gemm128_kernel<true><<<gemm_grid, 256>>>((const float*)pH, Wl, bl, out,
                                             T_LEN, D_DIM, D_DIM);

    // 5) residual + layernorm in-place on d_out
    layernorm_kernel<<<T_LEN, 256>>>(xs, ln_scale, ln_bias, out);
}